// round 3
// baseline (speedup 1.0000x reference)
#include <cuda_runtime.h>
#include <cstdint>

// FurthestPointsSample: x [B,3,N] f32 -> out [B,3,1024] f32. B=16, N=65536.
// 8-CTA cluster per batch; points register-resident (8/thread, packed f32x2)
// + SMEM mirror. Per round: f32x2 dist update, REDUX reductions, st.async
// key+coords all-to-all with mbarrier completion; ALL warps wait + reduce the
// 8 slots in parallel (no broadcast, one producer-consumer named barrier).

#define N_PTS   65536
#define CLUSTER 8
#define PPC     (N_PTS / CLUSTER)   // 8192
#define THREADS 1024
#define PPT     (PPC / THREADS)     // 8
#define NPAIR   (PPT / 2)           // 4
#define NPOINTS 1024
#define MSG_TX  20                  // bytes per source CTA: 8 key + 8 xy + 4 z

__device__ __forceinline__ unsigned ctarank() {
    unsigned r; asm("mov.u32 %0, %%cluster_ctarank;" : "=r"(r)); return r;
}
__device__ __forceinline__ void cluster_sync_all() {
    asm volatile("barrier.cluster.arrive.aligned;\n\t"
                 "barrier.cluster.wait.aligned;" ::: "memory");
}
__device__ __forceinline__ unsigned mapa_sh(unsigned addr, unsigned rank) {
    unsigned r;
    asm("mapa.shared::cluster.u32 %0, %1, %2;" : "=r"(r) : "r"(addr), "r"(rank));
    return r;
}
__device__ __forceinline__ unsigned long long addx2(unsigned long long a, unsigned long long b) {
    unsigned long long r; asm("add.rn.f32x2 %0, %1, %2;" : "=l"(r) : "l"(a), "l"(b)); return r;
}
__device__ __forceinline__ unsigned long long mulx2(unsigned long long a, unsigned long long b) {
    unsigned long long r; asm("mul.rn.f32x2 %0, %1, %2;" : "=l"(r) : "l"(a), "l"(b)); return r;
}
__device__ __forceinline__ unsigned long long packf2(float lo, float hi) {
    unsigned long long r; asm("mov.b64 %0, {%1, %2};" : "=l"(r) : "f"(lo), "f"(hi)); return r;
}
__device__ __forceinline__ void unpackf2(unsigned long long v, float& lo, float& hi) {
    asm("mov.b64 {%0, %1}, %2;" : "=f"(lo), "=f"(hi) : "l"(v));
}
__device__ __forceinline__ void st_async_u64(unsigned addr, unsigned long long v, unsigned mbar) {
    asm volatile("st.async.shared::cluster.mbarrier::complete_tx::bytes.b64 [%0], %1, [%2];"
                 :: "r"(addr), "l"(v), "r"(mbar) : "memory");
}
__device__ __forceinline__ void st_async_u32(unsigned addr, unsigned v, unsigned mbar) {
    asm volatile("st.async.shared::cluster.mbarrier::complete_tx::bytes.b32 [%0], %1, [%2];"
                 :: "r"(addr), "r"(v), "r"(mbar) : "memory");
}
__device__ __forceinline__ void mbar_init(unsigned addr, unsigned cnt) {
    asm volatile("mbarrier.init.shared.b64 [%0], %1;" :: "r"(addr), "r"(cnt) : "memory");
}
__device__ __forceinline__ void mbar_expect_tx(unsigned addr, unsigned tx) {
    asm volatile("mbarrier.arrive.expect_tx.shared.b64 _, [%0], %1;"
                 :: "r"(addr), "r"(tx) : "memory");
}
__device__ __forceinline__ void mbar_wait(unsigned addr, unsigned phase) {
    asm volatile(
        "{\n\t.reg .pred P;\n\t"
        "LAB_%=:\n\t"
        "mbarrier.try_wait.parity.acquire.cta.shared::cta.b64 P, [%0], %1, 0x989680;\n\t"
        "@!P bra LAB_%=;\n\t}"
        :: "r"(addr), "r"(phase) : "memory");
}
__device__ __forceinline__ void bar_arrive1() {
    asm volatile("bar.arrive 1, %0;" :: "r"(THREADS) : "memory");
}
__device__ __forceinline__ void bar_sync1() {
    asm volatile("bar.sync 1, %0;" :: "r"(THREADS) : "memory");
}

extern __shared__ float smem_dyn[];   // xs[8192] ys[8192] zs[8192] = 96 KB

__global__ void __launch_bounds__(THREADS, 1) __cluster_dims__(CLUSTER, 1, 1)
fps_cluster_kernel(const float* __restrict__ x, float* __restrict__ out)
{
    __shared__ unsigned long long warp_key[32];
    // slot layout (32 B): key u64 @0 | pad @8 | xy f32x2 @16 | z f32 @24
    __shared__ __align__(16) unsigned char slotmem[2][CLUSTER][32];
    __shared__ __align__(8) unsigned long long mbar[2];

    const unsigned r    = ctarank();
    const unsigned b    = blockIdx.x / CLUSTER;
    const unsigned tid  = threadIdx.x;
    const unsigned lane = tid & 31u;
    const unsigned wid  = tid >> 5;

    const float* __restrict__ xb = x + (size_t)b * 3u * N_PTS;
    const float* __restrict__ yb = xb + N_PTS;
    const float* __restrict__ zb = xb + 2 * N_PTS;
    float* __restrict__ ob = out + (size_t)b * 3u * NPOINTS;

    float* xs = smem_dyn;
    float* ys = xs + PPC;
    float* zs = ys + PPC;

    const unsigned slot_base = (unsigned)__cvta_generic_to_shared(&slotmem[0][0][0]);
    const unsigned bar_base  = (unsigned)__cvta_generic_to_shared(&mbar[0]);

    if (tid == 0) { mbar_init(bar_base, 1); mbar_init(bar_base + 8, 1); }

    // Load points into registers (packed pairs) + SMEM mirror.
    unsigned long long px2[NPAIR], py2[NPAIR], pz2[NPAIR];
    float dist[PPT];
    const unsigned gbase = r * PPC + tid;
#pragma unroll
    for (int p = 0; p < NPAIR; p++) {
        unsigned g0 = gbase + (unsigned)(2 * p) * THREADS;
        unsigned g1 = g0 + THREADS;
        float x0 = xb[g0], x1 = xb[g1];
        float y0 = yb[g0], y1 = yb[g1];
        float z0 = zb[g0], z1 = zb[g1];
        px2[p] = packf2(x0, x1); py2[p] = packf2(y0, y1); pz2[p] = packf2(z0, z1);
        unsigned l0 = tid + (unsigned)(2 * p) * THREADS, l1 = l0 + THREADS;
        xs[l0] = x0; xs[l1] = x1; ys[l0] = y0; ys[l1] = y1; zs[l0] = z0; zs[l1] = z1;
        dist[2 * p] = 1e10f; dist[2 * p + 1] = 1e10f;
    }
    __syncthreads();
    cluster_sync_all();   // peers' mbarriers + mirrors ready before any st.async

    // First selected point: index 0 (reference convention).
    float fx = __ldg(xb + 0), fy = __ldg(yb + 0), fz = __ldg(zb + 0);
    if (r == 0 && tid == 0) { ob[0] = fx; ob[NPOINTS] = fy; ob[2 * NPOINTS] = fz; }
    unsigned long long nlx2 = packf2(-fx, -fx);
    unsigned long long nly2 = packf2(-fy, -fy);
    unsigned long long nlz2 = packf2(-fz, -fz);

    unsigned ph0 = 0, ph1 = 0;

    for (int it = 1; it < NPOINTS; it++) {
        const int par = it & 1;
        const unsigned barp = bar_base + (unsigned)par * 8u;

        // Arm this round's barrier early (off the critical tail).
        if (tid == 0) mbar_expect_tx(barp, CLUSTER * MSG_TX);

        // ---- dist update (bit-exact) + FMNMX-only max tree ----
        float pmax[NPAIR];
#pragma unroll
        for (int p = 0; p < NPAIR; p++) {
            unsigned long long dx = addx2(px2[p], nlx2);
            unsigned long long dy = addx2(py2[p], nly2);
            unsigned long long dz = addx2(pz2[p], nlz2);
            unsigned long long s  = addx2(addx2(mulx2(dx, dx), mulx2(dy, dy)), mulx2(dz, dz));
            float s0, s1; unpackf2(s, s0, s1);
            float nd0 = fminf(dist[2 * p], s0);     dist[2 * p]     = nd0;
            float nd1 = fminf(dist[2 * p + 1], s1); dist[2 * p + 1] = nd1;
            pmax[p] = fmaxf(nd0, nd1);
        }
        float bestd = fmaxf(fmaxf(pmax[0], pmax[1]), fmaxf(pmax[2], pmax[3]));

        // First-occurrence index recovery: smallest j with dist[j] == bestd.
        int bestj = 0;
#pragma unroll
        for (int j = PPT - 1; j >= 0; j--)
            bestj = (dist[j] == bestd) ? j : bestj;

        // ---- warp reduction: max dist bits, then min global index ----
        unsigned bits = __float_as_uint(bestd);
        unsigned wmax = __reduce_max_sync(0xffffffffu, bits);
        unsigned g    = gbase + (unsigned)bestj * THREADS;
        unsigned cand = (bits == wmax) ? ~g : 0u;
        unsigned wi   = __reduce_max_sync(0xffffffffu, cand);
        if (lane == 0)
            warp_key[wid] = ((unsigned long long)wmax << 32) | wi;

        // Producer-consumer barrier: only warp 0 waits for all arrivals.
        if (wid != 0) {
            bar_arrive1();
        } else {
            bar_sync1();
            // ---- block reduction over 32 warp keys ----
            unsigned long long k = warp_key[lane];
            unsigned hb = (unsigned)(k >> 32);
            unsigned hm = __reduce_max_sync(0xffffffffu, hb);
            unsigned lo = (hb == hm) ? (unsigned)k : 0u;
            unsigned lm = __reduce_max_sync(0xffffffffu, lo);

            // ---- push {key, coords} to every CTA: lane t -> rank t ----
            if (lane < CLUSTER) {
                unsigned long long ckey = ((unsigned long long)hm << 32) | lm;
                unsigned local = (~lm) & (PPC - 1);     // block winner, CTA-local
                float wx = xs[local], wy = ys[local], wz = zs[local];
                unsigned lslot = slot_base + (unsigned)(par * CLUSTER + (int)r) * 32u;
                unsigned rslot = mapa_sh(lslot, lane);
                unsigned rbar  = mapa_sh(barp, lane);
                st_async_u64(rslot,      ckey,               rbar);
                st_async_u64(rslot + 16, packf2(wx, wy),     rbar);
                st_async_u32(rslot + 24, __float_as_uint(wz), rbar);
            }
        }

        // ---- ALL warps wait for the 8 messages, each reduces slots itself ----
        mbar_wait(barp, par ? ph1 : ph0);

        unsigned long long sk = 0ull;
        if (lane < CLUSTER)
            sk = *(const unsigned long long*)&slotmem[par][lane][0];
        unsigned shi = (unsigned)(sk >> 32);
        unsigned shm = __reduce_max_sync(0xffffffffu, shi);
        unsigned slo = (shi == shm) ? (unsigned)sk : 0u;
        unsigned slm = __reduce_max_sync(0xffffffffu, slo);
        // keys are distinct across CTAs (disjoint index ranges) -> unique slot
        unsigned bal = __ballot_sync(0xffffffffu,
                                     (lane < CLUSTER) && (shi == shm) && ((unsigned)sk == slm));
        int wslot = __ffs(bal) - 1;
        float2 xy = *(const float2*)&slotmem[par][wslot][16];
        float  wz = *(const float*)&slotmem[par][wslot][24];

        nlx2 = packf2(-xy.x, -xy.x);
        nly2 = packf2(-xy.y, -xy.y);
        nlz2 = packf2(-wz, -wz);

        if (r == 0 && tid == 0) {
            ob[it] = xy.x; ob[NPOINTS + it] = xy.y; ob[2 * NPOINTS + it] = wz;
        }
        if (par) ph1 ^= 1; else ph0 ^= 1;
    }
}

extern "C" void kernel_launch(void* const* d_in, const int* in_sizes, int n_in,
                              void* d_out, int out_size)
{
    const float* x = (const float*)d_in[0];
    float* out = (float*)d_out;
    int B = in_sizes[0] / (3 * N_PTS);   // 16
    size_t dyn = 3 * PPC * sizeof(float);   // 96 KB
    cudaFuncSetAttribute(fps_cluster_kernel,
                         cudaFuncAttributeMaxDynamicSharedMemorySize, (int)dyn);
    dim3 grid(B * CLUSTER), block(THREADS);
    fps_cluster_kernel<<<grid, block, dyn>>>(x, out);
}

// round 4
// speedup vs baseline: 1.1241x; 1.1241x over previous
#include <cuda_runtime.h>
#include <cstdint>

// FurthestPointsSample: x [B,3,N] f32 -> out [B,3,1024] f32. B=16, N=65536.
// 8-CTA cluster per batch; points register-resident (8/thread, packed f32x2)
// + SMEM mirror. Per round: f32x2 dist update, REDUX reductions, 16-byte
// st.async all-to-all {x,y,z,distbits} (tie-break = slot position, since rank
// ranges are contiguous), warp0-only mbar wait + slot reduce + smem broadcast.

#define N_PTS   65536
#define CLUSTER 8
#define PPC     (N_PTS / CLUSTER)   // 8192
#define THREADS 1024
#define PPT     (PPC / THREADS)     // 8
#define NPAIR   (PPT / 2)           // 4
#define NPOINTS 1024
#define MSG_TX  16                  // bytes per source CTA: 8 (x,y) + 8 (z,distbits)

__device__ __forceinline__ unsigned ctarank() {
    unsigned r; asm("mov.u32 %0, %%cluster_ctarank;" : "=r"(r)); return r;
}
__device__ __forceinline__ void cluster_sync_all() {
    asm volatile("barrier.cluster.arrive.aligned;\n\t"
                 "barrier.cluster.wait.aligned;" ::: "memory");
}
__device__ __forceinline__ unsigned mapa_sh(unsigned addr, unsigned rank) {
    unsigned r;
    asm("mapa.shared::cluster.u32 %0, %1, %2;" : "=r"(r) : "r"(addr), "r"(rank));
    return r;
}
__device__ __forceinline__ unsigned long long addx2(unsigned long long a, unsigned long long b) {
    unsigned long long r; asm("add.rn.f32x2 %0, %1, %2;" : "=l"(r) : "l"(a), "l"(b)); return r;
}
__device__ __forceinline__ unsigned long long mulx2(unsigned long long a, unsigned long long b) {
    unsigned long long r; asm("mul.rn.f32x2 %0, %1, %2;" : "=l"(r) : "l"(a), "l"(b)); return r;
}
__device__ __forceinline__ unsigned long long packf2(float lo, float hi) {
    unsigned long long r; asm("mov.b64 %0, {%1, %2};" : "=l"(r) : "f"(lo), "f"(hi)); return r;
}
__device__ __forceinline__ void unpackf2(unsigned long long v, float& lo, float& hi) {
    asm("mov.b64 {%0, %1}, %2;" : "=f"(lo), "=f"(hi) : "l"(v));
}
__device__ __forceinline__ unsigned long long pack_zu(float z, unsigned hi) {
    unsigned long long r; asm("mov.b64 %0, {%1, %2};" : "=l"(r) : "f"(z), "r"(hi)); return r;
}
__device__ __forceinline__ void st_async_u64(unsigned addr, unsigned long long v, unsigned mbar) {
    asm volatile("st.async.shared::cluster.mbarrier::complete_tx::bytes.b64 [%0], %1, [%2];"
                 :: "r"(addr), "l"(v), "r"(mbar) : "memory");
}
__device__ __forceinline__ void mbar_init(unsigned addr, unsigned cnt) {
    asm volatile("mbarrier.init.shared.b64 [%0], %1;" :: "r"(addr), "r"(cnt) : "memory");
}
__device__ __forceinline__ void mbar_expect_tx(unsigned addr, unsigned tx) {
    asm volatile("mbarrier.arrive.expect_tx.shared.b64 _, [%0], %1;"
                 :: "r"(addr), "r"(tx) : "memory");
}
__device__ __forceinline__ void mbar_wait(unsigned addr, unsigned phase) {
    asm volatile(
        "{\n\t.reg .pred P;\n\t"
        "LAB_%=:\n\t"
        "mbarrier.try_wait.parity.acquire.cta.shared::cta.b64 P, [%0], %1, 0x989680;\n\t"
        "@!P bra LAB_%=;\n\t}"
        :: "r"(addr), "r"(phase) : "memory");
}

extern __shared__ float smem_dyn[];   // xs[8192] ys[8192] zs[8192] = 96 KB

__global__ void __launch_bounds__(THREADS, 1) __cluster_dims__(CLUSTER, 1, 1)
fps_cluster_kernel(const float* __restrict__ x, float* __restrict__ out)
{
    __shared__ unsigned long long warp_key[32];
    // 16-byte slots: [x f32][y f32][z f32][distbits u32]
    __shared__ __align__(16) float slotmem[2][CLUSTER][4];
    __shared__ float4 bcast[2];
    __shared__ __align__(8) unsigned long long mbar[2];

    const unsigned r    = ctarank();
    const unsigned b    = blockIdx.x / CLUSTER;
    const unsigned tid  = threadIdx.x;
    const unsigned lane = tid & 31u;
    const unsigned wid  = tid >> 5;

    const float* __restrict__ xb = x + (size_t)b * 3u * N_PTS;
    const float* __restrict__ yb = xb + N_PTS;
    const float* __restrict__ zb = xb + 2 * N_PTS;
    float* __restrict__ ob = out + (size_t)b * 3u * NPOINTS;

    float* xs = smem_dyn;
    float* ys = xs + PPC;
    float* zs = ys + PPC;

    const unsigned slot_base = (unsigned)__cvta_generic_to_shared(&slotmem[0][0][0]);
    const unsigned bar_base  = (unsigned)__cvta_generic_to_shared(&mbar[0]);

    if (tid == 0) { mbar_init(bar_base, 1); mbar_init(bar_base + 8, 1); }

    // Load points into registers (packed pairs) + SMEM mirror.
    unsigned long long px2[NPAIR], py2[NPAIR], pz2[NPAIR];
    float dist[PPT];
    const unsigned gbase = r * PPC + tid;
#pragma unroll
    for (int p = 0; p < NPAIR; p++) {
        unsigned g0 = gbase + (unsigned)(2 * p) * THREADS;
        unsigned g1 = g0 + THREADS;
        float x0 = xb[g0], x1 = xb[g1];
        float y0 = yb[g0], y1 = yb[g1];
        float z0 = zb[g0], z1 = zb[g1];
        px2[p] = packf2(x0, x1); py2[p] = packf2(y0, y1); pz2[p] = packf2(z0, z1);
        unsigned l0 = tid + (unsigned)(2 * p) * THREADS, l1 = l0 + THREADS;
        xs[l0] = x0; xs[l1] = x1; ys[l0] = y0; ys[l1] = y1; zs[l0] = z0; zs[l1] = z1;
        dist[2 * p] = 1e10f; dist[2 * p + 1] = 1e10f;
    }
    __syncthreads();
    cluster_sync_all();   // peers' mbarriers initialized before any st.async

    // First selected point: index 0 (reference convention).
    float fx = __ldg(xb + 0), fy = __ldg(yb + 0), fz = __ldg(zb + 0);
    if (r == 0 && tid == 0) { ob[0] = fx; ob[NPOINTS] = fy; ob[2 * NPOINTS] = fz; }
    unsigned long long nlx2 = packf2(-fx, -fx);
    unsigned long long nly2 = packf2(-fy, -fy);
    unsigned long long nlz2 = packf2(-fz, -fz);

    unsigned ph0 = 0, ph1 = 0;

    for (int it = 1; it < NPOINTS; it++) {
        const int par = it & 1;
        const unsigned barp = bar_base + (unsigned)par * 8u;

        // Arm this round's barrier early (off the critical tail; tx may go
        // pending-negative if remote stores land first — that's legal).
        if (tid == 0) mbar_expect_tx(barp, CLUSTER * MSG_TX);

        // ---- dist update + thread-local argmax (bit-exact, first occurrence) ----
        float bestd = -1.0f; int bestj = 0;
#pragma unroll
        for (int p = 0; p < NPAIR; p++) {
            unsigned long long dx = addx2(px2[p], nlx2);
            unsigned long long dy = addx2(py2[p], nly2);
            unsigned long long dz = addx2(pz2[p], nlz2);
            unsigned long long s  = addx2(addx2(mulx2(dx, dx), mulx2(dy, dy)), mulx2(dz, dz));
            float s0, s1; unpackf2(s, s0, s1);
            float nd0 = fminf(dist[2 * p], s0);     dist[2 * p]     = nd0;
            float nd1 = fminf(dist[2 * p + 1], s1); dist[2 * p + 1] = nd1;
            bool c0 = nd0 > bestd; bestd = c0 ? nd0 : bestd; bestj = c0 ? 2 * p : bestj;
            bool c1 = nd1 > bestd; bestd = c1 ? nd1 : bestd; bestj = c1 ? 2 * p + 1 : bestj;
        }

        // ---- warp reduction: max dist bits, then min global index ----
        unsigned bits = __float_as_uint(bestd);
        unsigned wmax = __reduce_max_sync(0xffffffffu, bits);
        unsigned g    = gbase + (unsigned)bestj * THREADS;
        unsigned cand = (bits == wmax) ? ~g : 0u;
        unsigned wi   = __reduce_max_sync(0xffffffffu, cand);
        if (lane == 0)
            warp_key[wid] = ((unsigned long long)wmax << 32) | wi;
        __syncthreads();

        if (wid == 0) {
            // ---- block reduction over 32 warp keys ----
            unsigned long long k = warp_key[lane];
            unsigned hb = (unsigned)(k >> 32);
            unsigned hm = __reduce_max_sync(0xffffffffu, hb);
            unsigned lo = (hb == hm) ? (unsigned)k : 0u;
            unsigned lm = __reduce_max_sync(0xffffffffu, lo);

            // ---- push {x,y,z,distbits} (16 B) to every CTA: lane t -> rank t ----
            if (lane < CLUSTER) {
                unsigned local = (~lm) & (PPC - 1);     // block winner, CTA-local
                float wx = xs[local], wy = ys[local], wz = zs[local];
                unsigned lslot = slot_base + (unsigned)(par * CLUSTER + (int)r) * 16u;
                unsigned rslot = mapa_sh(lslot, lane);
                unsigned rbar  = mapa_sh(barp, lane);
                st_async_u64(rslot,     packf2(wx, wy), rbar);
                st_async_u64(rslot + 8, pack_zu(wz, hm), rbar);
            }

            // ---- warp0 waits for all 8 messages, reduces the slots ----
            mbar_wait(barp, par ? ph1 : ph0);

            float4 s = *(const float4*)&slotmem[par][lane & (CLUSTER - 1)][0];
            unsigned db = __float_as_uint(s.w);
            unsigned m  = __reduce_max_sync(0xffffffffu, db);
            // Cross-CTA tie-break: rank ranges are contiguous ascending, so
            // min global index == min rank == min slot == min lane here.
            unsigned bal = __ballot_sync(0xffffffffu, (lane < CLUSTER) && (db == m));
            if (lane == (unsigned)(__ffs(bal) - 1))
                bcast[par] = s;
        }
        __syncthreads();

        float4 w = bcast[par];
        nlx2 = packf2(-w.x, -w.x);
        nly2 = packf2(-w.y, -w.y);
        nlz2 = packf2(-w.z, -w.z);
        if (r == 0 && tid == 0) {
            ob[it] = w.x; ob[NPOINTS + it] = w.y; ob[2 * NPOINTS + it] = w.z;
        }
        if (par) ph1 ^= 1; else ph0 ^= 1;
    }
}

extern "C" void kernel_launch(void* const* d_in, const int* in_sizes, int n_in,
                              void* d_out, int out_size)
{
    const float* x = (const float*)d_in[0];
    float* out = (float*)d_out;
    int B = in_sizes[0] / (3 * N_PTS);   // 16
    size_t dyn = 3 * PPC * sizeof(float);   // 96 KB
    cudaFuncSetAttribute(fps_cluster_kernel,
                         cudaFuncAttributeMaxDynamicSharedMemorySize, (int)dyn);
    dim3 grid(B * CLUSTER), block(THREADS);
    fps_cluster_kernel<<<grid, block, dyn>>>(x, out);
}